// round 1
// baseline (speedup 1.0000x reference)
#include <cuda_runtime.h>
#include <math.h>

// Problem constants
static constexpr int Bn  = 512;    // batch
static constexpr int Nn  = 8192;   // pool
static constexpr int Dn  = 1024;   // pool dim
static constexpr int DAn = 512;    // z dim
static constexpr int Sn  = 8;      // aspects
static constexpr int DKn = 64;     // head dim
static constexpr int Jn  = Sn * DKn; // 512 flattened key/query dim

// Scratch (device globals; no allocation allowed)
__device__ float g_qt[Bn * Jn];        // w-weighted normalized queries  [512,512]
__device__ float g_knorm[Nn * Jn];     // normalized keys                [8192,512]

// ---------------------------------------------------------------------------
// K1: queries = z @ W_Q per aspect, L2-normalize over DK, fold softmax(w).
// grid 64 blocks (8 batch rows each), 256 threads.
// ---------------------------------------------------------------------------
__global__ void __launch_bounds__(256) k_queries(
    const float* __restrict__ z, const float* __restrict__ WQ,
    const float* __restrict__ logits)
{
    __shared__ float zsh[8][DAn];   // 16 KB
    __shared__ float qsh[8][Jn];    // 16 KB
    __shared__ float nsh[64];
    __shared__ float wsh[8];

    int t  = threadIdx.x;
    int b0 = blockIdx.x * 8;

    for (int i = t; i < 8 * DAn; i += 256)
        zsh[i >> 9][i & 511] = z[(b0 + (i >> 9)) * DAn + (i & 511)];

    if (t == 0) {
        float m = logits[0];
        for (int i = 1; i < Sn; i++) m = fmaxf(m, logits[i]);
        float ssum = 0.f;
        for (int i = 0; i < Sn; i++) { float e = expf(logits[i] - m); wsh[i] = e; ssum += e; }
        for (int i = 0; i < Sn; i++) wsh[i] /= ssum;
    }
    __syncthreads();

    int c0 = t, c1 = t + 256;
    int a0 = c0 >> 6, q0 = c0 & 63;
    int a1 = c1 >> 6, q1 = c1 & 63;
    const float* wq0 = WQ + a0 * DAn * DKn + q0;
    const float* wq1 = WQ + a1 * DAn * DKn + q1;

    float acc0[8], acc1[8];
#pragma unroll
    for (int bb = 0; bb < 8; bb++) { acc0[bb] = 0.f; acc1[bb] = 0.f; }

    for (int p = 0; p < DAn; p++) {
        float w0 = wq0[p * DKn];
        float w1 = wq1[p * DKn];
#pragma unroll
        for (int bb = 0; bb < 8; bb++) {
            float zv = zsh[bb][p];
            acc0[bb] = fmaf(zv, w0, acc0[bb]);
            acc1[bb] = fmaf(zv, w1, acc1[bb]);
        }
    }
#pragma unroll
    for (int bb = 0; bb < 8; bb++) { qsh[bb][c0] = acc0[bb]; qsh[bb][c1] = acc1[bb]; }
    __syncthreads();

    if (t < 64) {
        int bb = t >> 3, a = t & 7;
        float ss = 0.f;
        for (int q = 0; q < DKn; q++) { float v = qsh[bb][a * DKn + q]; ss = fmaf(v, v, ss); }
        nsh[t] = sqrtf(ss);
    }
    __syncthreads();

#pragma unroll
    for (int bb = 0; bb < 8; bb++) {
        g_qt[(b0 + bb) * Jn + c0] = wsh[a0] * qsh[bb][c0] / (nsh[bb * 8 + a0] + 1e-8f);
        g_qt[(b0 + bb) * Jn + c1] = wsh[a1] * qsh[bb][c1] / (nsh[bb * 8 + a1] + 1e-8f);
    }
}

// ---------------------------------------------------------------------------
// K2: keys[n, a*64+q] = sum_p pool[n,p] * W_K[a,p,q]
// C[8192,512] = A[8192,1024] * B[1024,512]  (B gathered from W_K layout)
// 128x128 tile, BK=8, 256 threads, 8x8 microtile. grid (4, 64).
// ---------------------------------------------------------------------------
__global__ void __launch_bounds__(256) k_keys_gemm(
    const float* __restrict__ A, const float* __restrict__ WK,
    float* __restrict__ C)
{
    __shared__ float As[8][128];
    __shared__ float Bs[8][128];

    int t  = threadIdx.x;
    int j0 = blockIdx.x * 128;
    int m0 = blockIdx.y * 128;
    int tx = t & 15, ty = t >> 4;

    int ar = t >> 1, ac = (t & 1) * 4;           // A load: row ar, 4 cols at ac
    int bk = t >> 5, bj = (t & 31) * 4;          // B load: k row bk, 4 j at bj
    int jj = j0 + bj;
    int aAsp = jj >> 6, qq = jj & 63;

    const float* aptr = A + (m0 + ar) * Dn + ac;
    const float* bptr = WK + aAsp * (Dn * DKn) + bk * DKn + qq;

    float acc[8][8];
#pragma unroll
    for (int i = 0; i < 8; i++)
#pragma unroll
        for (int j = 0; j < 8; j++) acc[i][j] = 0.f;

    for (int k0 = 0; k0 < Dn; k0 += 8) {
        float4 av = *(const float4*)(aptr + k0);
        float4 bv = *(const float4*)(bptr + k0 * DKn);
        As[ac + 0][ar] = av.x; As[ac + 1][ar] = av.y;
        As[ac + 2][ar] = av.z; As[ac + 3][ar] = av.w;
        *(float4*)&Bs[bk][bj] = bv;
        __syncthreads();

#pragma unroll
        for (int kk = 0; kk < 8; kk++) {
            float4 a0 = *(const float4*)&As[kk][ty * 8];
            float4 a1 = *(const float4*)&As[kk][ty * 8 + 4];
            float4 b0 = *(const float4*)&Bs[kk][tx * 8];
            float4 b1 = *(const float4*)&Bs[kk][tx * 8 + 4];
            float af[8] = {a0.x, a0.y, a0.z, a0.w, a1.x, a1.y, a1.z, a1.w};
            float bf[8] = {b0.x, b0.y, b0.z, b0.w, b1.x, b1.y, b1.z, b1.w};
#pragma unroll
            for (int i = 0; i < 8; i++)
#pragma unroll
                for (int j = 0; j < 8; j++) acc[i][j] = fmaf(af[i], bf[j], acc[i][j]);
        }
        __syncthreads();
    }

#pragma unroll
    for (int i = 0; i < 8; i++) {
        int row = m0 + ty * 8 + i;
        float4 v0 = make_float4(acc[i][0], acc[i][1], acc[i][2], acc[i][3]);
        float4 v1 = make_float4(acc[i][4], acc[i][5], acc[i][6], acc[i][7]);
        *(float4*)&C[row * Jn + j0 + tx * 8]     = v0;
        *(float4*)&C[row * Jn + j0 + tx * 8 + 4] = v1;
    }
}

// ---------------------------------------------------------------------------
// K3: L2-normalize keys per (n, aspect) into g_knorm. warp per (n,a).
// grid 8192 blocks x 256 threads (8 warps).
// ---------------------------------------------------------------------------
__global__ void __launch_bounds__(256) k_knorm(const float* __restrict__ keys)
{
    int warp = threadIdx.x >> 5, lane = threadIdx.x & 31;
    int pair = blockIdx.x * 8 + warp;          // pair = n*8 + a, < 65536
    const float* src = keys + (size_t)pair * 64;
    float v0 = src[lane], v1 = src[lane + 32];
    float ss = v0 * v0 + v1 * v1;
#pragma unroll
    for (int off = 16; off > 0; off >>= 1)
        ss += __shfl_xor_sync(0xffffffffu, ss, off);
    float inv = 1.f / (sqrtf(ss) + 1e-8f);
    g_knorm[(size_t)pair * 64 + lane]      = v0 * inv;
    g_knorm[(size_t)pair * 64 + lane + 32] = v1 * inv;
}

// ---------------------------------------------------------------------------
// K4: scores[b,n] = dot(g_qt[b,:], g_knorm[n,:])   (NT GEMM, K=512)
// 128x128 tile, BK=8, 256 threads. grid (64, 4).
// ---------------------------------------------------------------------------
__global__ void __launch_bounds__(256) k_scores_gemm(float* __restrict__ C)
{
    __shared__ float As[8][128];
    __shared__ float Bs[8][128];

    int t  = threadIdx.x;
    int n0 = blockIdx.x * 128;
    int m0 = blockIdx.y * 128;
    int tx = t & 15, ty = t >> 4;

    int ar = t >> 1, ac = (t & 1) * 4;

    float acc[8][8];
#pragma unroll
    for (int i = 0; i < 8; i++)
#pragma unroll
        for (int j = 0; j < 8; j++) acc[i][j] = 0.f;

    for (int k0 = 0; k0 < Jn; k0 += 8) {
        float4 av = *(const float4*)&g_qt[(m0 + ar) * Jn + k0 + ac];
        float4 bv = *(const float4*)&g_knorm[(size_t)(n0 + ar) * Jn + k0 + ac];
        As[ac + 0][ar] = av.x; As[ac + 1][ar] = av.y;
        As[ac + 2][ar] = av.z; As[ac + 3][ar] = av.w;
        Bs[ac + 0][ar] = bv.x; Bs[ac + 1][ar] = bv.y;
        Bs[ac + 2][ar] = bv.z; Bs[ac + 3][ar] = bv.w;
        __syncthreads();

#pragma unroll
        for (int kk = 0; kk < 8; kk++) {
            float4 a0 = *(const float4*)&As[kk][ty * 8];
            float4 a1 = *(const float4*)&As[kk][ty * 8 + 4];
            float4 b0 = *(const float4*)&Bs[kk][tx * 8];
            float4 b1 = *(const float4*)&Bs[kk][tx * 8 + 4];
            float af[8] = {a0.x, a0.y, a0.z, a0.w, a1.x, a1.y, a1.z, a1.w};
            float bf[8] = {b0.x, b0.y, b0.z, b0.w, b1.x, b1.y, b1.z, b1.w};
#pragma unroll
            for (int i = 0; i < 8; i++)
#pragma unroll
                for (int j = 0; j < 8; j++) acc[i][j] = fmaf(af[i], bf[j], acc[i][j]);
        }
        __syncthreads();
    }

#pragma unroll
    for (int i = 0; i < 8; i++) {
        int row = m0 + ty * 8 + i;
        float4 v0 = make_float4(acc[i][0], acc[i][1], acc[i][2], acc[i][3]);
        float4 v1 = make_float4(acc[i][4], acc[i][5], acc[i][6], acc[i][7]);
        *(float4*)&C[(size_t)row * Nn + n0 + tx * 8]     = v0;
        *(float4*)&C[(size_t)row * Nn + n0 + tx * 8 + 4] = v1;
    }
}

// ---------------------------------------------------------------------------
// K5: gate + temperature-scaled normalize -> alpha. One block per batch row.
// ---------------------------------------------------------------------------
__global__ void __launch_bounds__(256) k_alpha(
    const float* __restrict__ scores, float* __restrict__ alpha,
    const float* __restrict__ ptau, const float* __restrict__ plam,
    const float* __restrict__ ptemp)
{
    __shared__ float raw[Nn];       // 32 KB
    __shared__ float red[8];
    __shared__ float stot;

    int t = threadIdx.x, b = blockIdx.x;
    float tau = *ptau, lam = *plam, invT = 1.f / (*ptemp);

    float s_local = 0.f;
    for (int i = t; i < Nn; i += 256) {
        float s = scores[(size_t)b * Nn + i];
        float g = 1.f / (1.f + expf(-lam * (s - tau)));
        float r = g * expf(s * invT);
        raw[i] = r;
        s_local += r;
    }
#pragma unroll
    for (int off = 16; off > 0; off >>= 1)
        s_local += __shfl_xor_sync(0xffffffffu, s_local, off);
    if ((t & 31) == 0) red[t >> 5] = s_local;
    __syncthreads();
    if (t == 0) {
        float s = 0.f;
        for (int w = 0; w < 8; w++) s += red[w];
        stot = s;
    }
    __syncthreads();

    float inv = 1.f / (stot + 1e-8f);
    for (int i = t; i < Nn; i += 256)
        alpha[(size_t)b * Nn + i] = raw[i] * inv;
}

// ---------------------------------------------------------------------------
extern "C" void kernel_launch(void* const* d_in, const int* in_sizes, int n_in,
                              void* d_out, int out_size)
{
    const float* z      = (const float*)d_in[0];
    const float* pool   = (const float*)d_in[1];
    const float* WQ     = (const float*)d_in[2];
    const float* WK     = (const float*)d_in[3];
    const float* logits = (const float*)d_in[4];
    const float* tau    = (const float*)d_in[5];
    const float* lam    = (const float*)d_in[6];
    const float* temp   = (const float*)d_in[7];

    float* alpha  = (float*)d_out;
    float* scores = alpha  + (size_t)Bn * Nn;
    float* keys   = scores + (size_t)Bn * Nn;

    k_queries<<<Bn / 8, 256>>>(z, WQ, logits);
    k_keys_gemm<<<dim3(Jn / 128, Nn / 128), 256>>>(pool, WK, keys);
    k_knorm<<<Nn * Sn / 8, 256>>>(keys);
    k_scores_gemm<<<dim3(Nn / 128, Bn / 128), 256>>>(scores);
    k_alpha<<<Bn, 256>>>(scores, alpha, tau, lam, temp);
}

// round 4
// speedup vs baseline: 1.8597x; 1.8597x over previous
#include <cuda_runtime.h>
#include <cuda_bf16.h>
#include <cstdint>
#include <math.h>

// Problem constants
static constexpr int Bn  = 512;    // batch
static constexpr int Nn  = 8192;   // pool
static constexpr int Dn  = 1024;   // pool dim
static constexpr int DAn = 512;    // z dim
static constexpr int Sn  = 8;      // aspects
static constexpr int DKn = 64;     // head dim
static constexpr int Jn  = Sn * DKn; // 512 flattened key/query dim

// ---------------------------------------------------------------------------
// Scratch (device globals; no allocation allowed)
// ---------------------------------------------------------------------------
__device__ __nv_bfloat16 g_Ah[Nn * Dn];   // pool hi   [8192,1024]
__device__ __nv_bfloat16 g_Al[Nn * Dn];   // pool lo
__device__ __nv_bfloat16 g_BhT[Jn * Dn];  // W_K^T hi  [512,1024] (j=a*64+q, p)
__device__ __nv_bfloat16 g_BlT[Jn * Dn];  // W_K^T lo
__device__ __nv_bfloat16 g_Qh[Bn * Jn];   // weighted normalized queries hi [512,512]
__device__ __nv_bfloat16 g_Ql[Bn * Jn];
__device__ __nv_bfloat16 g_Kh[Nn * Jn];   // normalized keys hi [8192,512]
__device__ __nv_bfloat16 g_Kl[Nn * Jn];

// ---------------------------------------------------------------------------
// helpers
// ---------------------------------------------------------------------------
__device__ __forceinline__ uint32_t smem_to_u32(const void* smem_ptr) {
    uint32_t addr;
    asm("{ .reg .u64 tmp; cvta.to.shared.u64 tmp, %1; cvt.u32.u64 %0, tmp; }"
        : "=r"(addr) : "l"(smem_ptr));
    return addr;
}

__device__ __forceinline__ void cp16(uint32_t dst, const void* src) {
    asm volatile("cp.async.cg.shared.global [%0], [%1], 16;"
                 :: "r"(dst), "l"(src) : "memory");
}
#define CP_COMMIT() asm volatile("cp.async.commit_group;" ::: "memory")
#define CP_WAIT0()  asm volatile("cp.async.wait_group 0;" ::: "memory")

__device__ __forceinline__ void ldsm_x4(uint32_t* r, uint32_t addr) {
    asm volatile("ldmatrix.sync.aligned.m8n8.x4.shared.b16 {%0,%1,%2,%3}, [%4];"
                 : "=r"(r[0]), "=r"(r[1]), "=r"(r[2]), "=r"(r[3]) : "r"(addr));
}

__device__ __forceinline__ void mma_bf16(float* c, const uint32_t* a, const uint32_t* b) {
    asm volatile(
        "mma.sync.aligned.m16n8k16.row.col.f32.bf16.bf16.f32 "
        "{%0,%1,%2,%3}, {%4,%5,%6,%7}, {%8,%9}, {%0,%1,%2,%3};"
        : "+f"(c[0]), "+f"(c[1]), "+f"(c[2]), "+f"(c[3])
        : "r"(a[0]), "r"(a[1]), "r"(a[2]), "r"(a[3]), "r"(b[0]), "r"(b[1]));
}

#define SWZ(off) ((off) ^ (((off) >> 3) & 0x70))

__device__ __forceinline__ void bf16_split(float v, __nv_bfloat16& h, __nv_bfloat16& l) {
    h = __float2bfloat16(v);
    l = __float2bfloat16(v - __bfloat162float(h));
}

// ---------------------------------------------------------------------------
// K0a: split pool fp32 -> bf16 hi/lo. float4 per thread.
// ---------------------------------------------------------------------------
__global__ void __launch_bounds__(256) k_split_pool(const float* __restrict__ X)
{
    int i = blockIdx.x * 256 + threadIdx.x;  // float4 index
    float4 v = ((const float4*)X)[i];
    __nv_bfloat16 h0, h1, h2, h3, l0, l1, l2, l3;
    bf16_split(v.x, h0, l0); bf16_split(v.y, h1, l1);
    bf16_split(v.z, h2, l2); bf16_split(v.w, h3, l3);
    __nv_bfloat162* H2 = (__nv_bfloat162*)g_Ah;
    __nv_bfloat162* L2 = (__nv_bfloat162*)g_Al;
    __nv_bfloat162 a; a.x = h0; a.y = h1;
    __nv_bfloat162 b; b.x = h2; b.y = h3;
    __nv_bfloat162 c; c.x = l0; c.y = l1;
    __nv_bfloat162 d; d.x = l2; d.y = l3;
    H2[2 * i] = a; H2[2 * i + 1] = b;
    L2[2 * i] = c; L2[2 * i + 1] = d;
}

// ---------------------------------------------------------------------------
// K0b: W_K[a,p,q] -> transposed split BhT/BlT[j=a*64+q, p].
// ---------------------------------------------------------------------------
__global__ void __launch_bounds__(256) k_split_wkT(const float* __restrict__ WK)
{
    int idx = blockIdx.x * 256 + threadIdx.x;   // over 512*1024
    int j = idx >> 10, p = idx & 1023;
    int a = j >> 6, q = j & 63;
    float v = WK[a * (Dn * DKn) + p * DKn + q];
    __nv_bfloat16 h, l;
    bf16_split(v, h, l);
    g_BhT[idx] = h;
    g_BlT[idx] = l;
}

// ---------------------------------------------------------------------------
// K1: queries = z @ W_Q, L2-normalize over DK, fold softmax(w), split bf16.
// ---------------------------------------------------------------------------
__global__ void __launch_bounds__(256) k_queries(
    const float* __restrict__ z, const float* __restrict__ WQ,
    const float* __restrict__ logits)
{
    __shared__ float zsh[8][DAn];
    __shared__ float qsh[8][Jn];
    __shared__ float nsh[64];
    __shared__ float wsh[8];

    int t  = threadIdx.x;
    int b0 = blockIdx.x * 8;

    for (int i = t; i < 8 * DAn; i += 256)
        zsh[i >> 9][i & 511] = z[(b0 + (i >> 9)) * DAn + (i & 511)];

    if (t == 0) {
        float m = logits[0];
        for (int i = 1; i < Sn; i++) m = fmaxf(m, logits[i]);
        float ssum = 0.f;
        for (int i = 0; i < Sn; i++) { float e = expf(logits[i] - m); wsh[i] = e; ssum += e; }
        for (int i = 0; i < Sn; i++) wsh[i] /= ssum;
    }
    __syncthreads();

    int c0 = t, c1 = t + 256;
    int a0 = c0 >> 6;
    int a1 = c1 >> 6;
    const float* wq0 = WQ + a0 * DAn * DKn + (c0 & 63);
    const float* wq1 = WQ + a1 * DAn * DKn + (c1 & 63);

    float acc0[8], acc1[8];
#pragma unroll
    for (int bb = 0; bb < 8; bb++) { acc0[bb] = 0.f; acc1[bb] = 0.f; }

    for (int p = 0; p < DAn; p++) {
        float w0 = wq0[p * DKn];
        float w1 = wq1[p * DKn];
#pragma unroll
        for (int bb = 0; bb < 8; bb++) {
            float zv = zsh[bb][p];
            acc0[bb] = fmaf(zv, w0, acc0[bb]);
            acc1[bb] = fmaf(zv, w1, acc1[bb]);
        }
    }
#pragma unroll
    for (int bb = 0; bb < 8; bb++) { qsh[bb][c0] = acc0[bb]; qsh[bb][c1] = acc1[bb]; }
    __syncthreads();

    if (t < 64) {
        int bb = t >> 3, a = t & 7;
        float ss = 0.f;
        for (int q = 0; q < DKn; q++) { float v = qsh[bb][a * DKn + q]; ss = fmaf(v, v, ss); }
        nsh[t] = sqrtf(ss);
    }
    __syncthreads();

#pragma unroll
    for (int bb = 0; bb < 8; bb++) {
        float v0 = wsh[a0] * qsh[bb][c0] / (nsh[bb * 8 + a0] + 1e-8f);
        float v1 = wsh[a1] * qsh[bb][c1] / (nsh[bb * 8 + a1] + 1e-8f);
        __nv_bfloat16 h, l;
        bf16_split(v0, h, l);
        g_Qh[(b0 + bb) * Jn + c0] = h;
        g_Ql[(b0 + bb) * Jn + c0] = l;
        bf16_split(v1, h, l);
        g_Qh[(b0 + bb) * Jn + c1] = h;
        g_Ql[(b0 + bb) * Jn + c1] = l;
    }
}

// ---------------------------------------------------------------------------
// Split-3 bf16 GEMM on mma.sync (HMMA):
//   C[M,N] = Ah*Bh^T + Al*Bh^T + Ah*Bl^T   (fused per k-step)
// 128x128 block tile, BK=64, 256 threads (8 warps, 4m x 2n), warp tile 32x64.
// 2-stage cp.async double buffer, SW128-swizzled smem, ldmatrix fragments.
// Dynamic smem: 2 stages * 4 tiles * 16KB = 128KB.
// ---------------------------------------------------------------------------
__global__ void __launch_bounds__(256)
k_gemm_bf16x3(
    const __nv_bfloat16* __restrict__ Ah, const __nv_bfloat16* __restrict__ Al,
    const __nv_bfloat16* __restrict__ Bh, const __nv_bfloat16* __restrict__ Bl,
    float* __restrict__ C, int Ktot, int ldC)
{
    extern __shared__ __align__(1024) uint8_t smem[];
    constexpr uint32_t TILE  = 128 * 128;       // 16 KB per operand tile
    constexpr uint32_t STAGE = 4 * TILE;        // 64 KB per stage

    const int t    = threadIdx.x;
    const int lane = t & 31;
    const int wid  = t >> 5;
    const int warpM = wid & 3;                  // 0..3 -> m offset 32*warpM
    const int warpN = wid >> 2;                 // 0..1 -> n offset 64*warpN
    const int m0 = blockIdx.y * 128;
    const int n0 = blockIdx.x * 128;

    const uint32_t smem_u = smem_to_u32(smem);

    // --- stage loader: 16 cp.async of 16B per thread ---
    auto load_stage = [&](int kt, int s) {
        uint32_t base = smem_u + (uint32_t)s * STAGE;
        int koff = kt * 64;
#pragma unroll
        for (int i = 0; i < 4; i++) {
            int c   = t + i * 256;              // 0..1023
            int row = c >> 3, grp = c & 7;
            uint32_t soff = SWZ((uint32_t)(row * 128 + grp * 16));
            size_t aoff = (size_t)(m0 + row) * Ktot + koff + grp * 8;
            size_t boff = (size_t)(n0 + row) * Ktot + koff + grp * 8;
            cp16(base + soff,            Ah + aoff);
            cp16(base + TILE + soff,     Al + aoff);
            cp16(base + 2 * TILE + soff, Bh + boff);
            cp16(base + 3 * TILE + soff, Bl + boff);
        }
    };

    // --- ldmatrix relative coordinates ---
    const int arow  = warpM * 32 + (lane & 15);  // + mi*16
    const int acolg = (lane >> 4) * 16;          // 0 or 16 bytes (k group)
    const int bg    = lane >> 3;                 // 0..3 matrix select
    const int brow  = warpN * 64 + ((bg >= 2) ? 8 : 0) + (lane & 7); // + njp*16
    const int bcol  = (bg & 1) * 16;             // k group bytes

    float acc[2][8][4];
#pragma unroll
    for (int mi = 0; mi < 2; mi++)
#pragma unroll
        for (int nj = 0; nj < 8; nj++)
#pragma unroll
            for (int r = 0; r < 4; r++) acc[mi][nj][r] = 0.f;

    const int KT = Ktot >> 6;
    load_stage(0, 0);
    CP_COMMIT();

    for (int kt = 0; kt < KT; kt++) {
        CP_WAIT0();
        __syncthreads();
        if (kt + 1 < KT) { load_stage(kt + 1, (kt + 1) & 1); }
        CP_COMMIT();

        uint32_t base = smem_u + (uint32_t)(kt & 1) * STAGE;

#pragma unroll
        for (int ks = 0; ks < 4; ks++) {
            uint32_t ah[2][4], al[2][4], bh[4][4], bl[4][4];
#pragma unroll
            for (int mi = 0; mi < 2; mi++) {
                uint32_t off = SWZ((uint32_t)((arow + mi * 16) * 128 + ks * 32 + acolg));
                ldsm_x4(ah[mi], base + off);
                ldsm_x4(al[mi], base + TILE + off);
            }
#pragma unroll
            for (int njp = 0; njp < 4; njp++) {
                uint32_t off = SWZ((uint32_t)((brow + njp * 16) * 128 + ks * 32 + bcol));
                ldsm_x4(bh[njp], base + 2 * TILE + off);
                ldsm_x4(bl[njp], base + 3 * TILE + off);
            }
#pragma unroll
            for (int mi = 0; mi < 2; mi++)
#pragma unroll
                for (int nj = 0; nj < 8; nj++) {
                    const uint32_t* bhf = &bh[nj >> 1][(nj & 1) * 2];
                    const uint32_t* blf = &bl[nj >> 1][(nj & 1) * 2];
                    mma_bf16(acc[mi][nj], ah[mi], bhf);
                    mma_bf16(acc[mi][nj], al[mi], bhf);
                    mma_bf16(acc[mi][nj], ah[mi], blf);
                }
        }
        __syncthreads();
    }

    // --- epilogue: write fp32 accumulators ---
#pragma unroll
    for (int mi = 0; mi < 2; mi++) {
        int r0 = m0 + warpM * 32 + mi * 16 + (lane >> 2);
        int r1 = r0 + 8;
#pragma unroll
        for (int nj = 0; nj < 8; nj++) {
            int col = n0 + warpN * 64 + nj * 8 + (lane & 3) * 2;
            *(float2*)&C[(size_t)r0 * ldC + col] = make_float2(acc[mi][nj][0], acc[mi][nj][1]);
            *(float2*)&C[(size_t)r1 * ldC + col] = make_float2(acc[mi][nj][2], acc[mi][nj][3]);
        }
    }
}

// ---------------------------------------------------------------------------
// K3: L2-normalize keys per (n, aspect), write bf16 hi/lo splits.
// ---------------------------------------------------------------------------
__global__ void __launch_bounds__(256) k_knorm_split(const float* __restrict__ keys)
{
    int warp = threadIdx.x >> 5, lane = threadIdx.x & 31;
    int pair = blockIdx.x * 8 + warp;          // pair = n*8 + a
    const float* src = keys + (size_t)pair * 64;
    float v0 = src[lane], v1 = src[lane + 32];
    float ss = v0 * v0 + v1 * v1;
#pragma unroll
    for (int off = 16; off > 0; off >>= 1)
        ss += __shfl_xor_sync(0xffffffffu, ss, off);
    float inv = 1.f / (sqrtf(ss) + 1e-8f);
    v0 *= inv; v1 *= inv;
    __nv_bfloat16 h, l;
    bf16_split(v0, h, l);
    g_Kh[(size_t)pair * 64 + lane] = h;
    g_Kl[(size_t)pair * 64 + lane] = l;
    bf16_split(v1, h, l);
    g_Kh[(size_t)pair * 64 + lane + 32] = h;
    g_Kl[(size_t)pair * 64 + lane + 32] = l;
}

// ---------------------------------------------------------------------------
// K5: gate + temperature-scaled normalize -> alpha. One block per batch row.
// ---------------------------------------------------------------------------
__global__ void __launch_bounds__(256) k_alpha(
    const float* __restrict__ scores, float* __restrict__ alpha,
    const float* __restrict__ ptau, const float* __restrict__ plam,
    const float* __restrict__ ptemp)
{
    __shared__ float raw[Nn];       // 32 KB
    __shared__ float red[8];
    __shared__ float stot;

    int t = threadIdx.x, b = blockIdx.x;
    float tau = *ptau, lam = *plam, invT = 1.f / (*ptemp);

    float s_local = 0.f;
    for (int i = t; i < Nn; i += 256) {
        float s = scores[(size_t)b * Nn + i];
        float g = 1.f / (1.f + expf(-lam * (s - tau)));
        float r = g * expf(s * invT);
        raw[i] = r;
        s_local += r;
    }
#pragma unroll
    for (int off = 16; off > 0; off >>= 1)
        s_local += __shfl_xor_sync(0xffffffffu, s_local, off);
    if ((t & 31) == 0) red[t >> 5] = s_local;
    __syncthreads();
    if (t == 0) {
        float s = 0.f;
        for (int w = 0; w < 8; w++) s += red[w];
        stot = s;
    }
    __syncthreads();

    float inv = 1.f / (stot + 1e-8f);
    for (int i = t; i < Nn; i += 256)
        alpha[(size_t)b * Nn + i] = raw[i] * inv;
}

// ---------------------------------------------------------------------------
extern "C" void kernel_launch(void* const* d_in, const int* in_sizes, int n_in,
                              void* d_out, int out_size)
{
    const float* z      = (const float*)d_in[0];
    const float* pool   = (const float*)d_in[1];
    const float* WQ     = (const float*)d_in[2];
    const float* WK     = (const float*)d_in[3];
    const float* logits = (const float*)d_in[4];
    const float* tau    = (const float*)d_in[5];
    const float* lam    = (const float*)d_in[6];
    const float* temp   = (const float*)d_in[7];

    float* alpha  = (float*)d_out;
    float* scores = alpha  + (size_t)Bn * Nn;
    float* keys   = scores + (size_t)Bn * Nn;

    __nv_bfloat16 *Ah, *Al, *BhT, *BlT, *Qh, *Ql, *Kh, *Kl;
    cudaGetSymbolAddress((void**)&Ah,  g_Ah);
    cudaGetSymbolAddress((void**)&Al,  g_Al);
    cudaGetSymbolAddress((void**)&BhT, g_BhT);
    cudaGetSymbolAddress((void**)&BlT, g_BlT);
    cudaGetSymbolAddress((void**)&Qh,  g_Qh);
    cudaGetSymbolAddress((void**)&Ql,  g_Ql);
    cudaGetSymbolAddress((void**)&Kh,  g_Kh);
    cudaGetSymbolAddress((void**)&Kl,  g_Kl);

    // No static guard (contract: kernel_launch must be stateless/deterministic).
    // cudaFuncSetAttribute is not a stream operation; safe under graph capture.
    cudaFuncSetAttribute(k_gemm_bf16x3,
                         cudaFuncAttributeMaxDynamicSharedMemorySize, 131072);

    // operand preparation
    k_split_pool<<<(Nn * Dn / 4) / 256, 256>>>(pool);
    k_split_wkT<<<(Jn * Dn) / 256, 256>>>(WK);
    k_queries<<<Bn / 8, 256>>>(z, WQ, logits);

    // keys[8192,512] = pool[8192,1024] @ WkT[512,1024]^T   (bf16 split-3)
    k_gemm_bf16x3<<<dim3(Jn / 128, Nn / 128), 256, 131072>>>(Ah, Al, BhT, BlT,
                                                             keys, Dn, Jn);

    // normalize keys, split to bf16
    k_knorm_split<<<Nn, 256>>>(keys);

    // scores[512,8192] = Qt[512,512] @ Khat[8192,512]^T    (bf16 split-3)
    k_gemm_bf16x3<<<dim3(Nn / 128, Bn / 128), 256, 131072>>>(Qh, Ql, Kh, Kl,
                                                             scores, Jn, Nn);

    k_alpha<<<Bn, 256>>>(scores, alpha, tau, lam, temp);
}